// round 4
// baseline (speedup 1.0000x reference)
#include <cuda_runtime.h>
#include <cuda_fp16.h>
#include <cstdint>
#include <math.h>

// Problem constants (fixed for this problem instance)
#define OUT_FEATURES 11008
#define IN_FEATURES  4096
#define TOKENS       64
#define BLOCK_SIZE   1024
#define NUM_BLOCKS   (OUT_FEATURES * IN_FEATURES / BLOCK_SIZE)   // 44032
#define W_ELEMS      ((long)OUT_FEATURES * IN_FEATURES)          // 45,088,768

// Scratch (no allocation allowed -> device globals)
__device__ __half g_W[W_ELEMS];                       // dequantized weights, fp16
__device__ __half g_x[TOKENS * IN_FEATURES];          // x converted to fp16
__device__ int    g_qflag;                            // 0 = int8 layout, 1 = int32, 2 = float32

// ---------------------------------------------------------------------------
// Kernel 0: detect the storage layout of int8_data (the harness may upcast).
// Majority vote over the first 64 32-bit words.
// ---------------------------------------------------------------------------
__global__ void detect_kernel(const void* __restrict__ qdata)
{
    __shared__ int c_i32, c_f32;
    if (threadIdx.x == 0) { c_i32 = 0; c_f32 = 0; }
    __syncthreads();

    const int t = threadIdx.x;   // 64 threads
    int w = ((const int*)qdata)[t];
    bool vi32 = (w >= -127 && w <= 127);
    float f = __int_as_float(w);
    bool vf32 = (!vi32) && isfinite(f) && fabsf(f) <= 127.0f && f == truncf(f);
    if (vi32) atomicAdd(&c_i32, 1);
    if (vf32) atomicAdd(&c_f32, 1);
    __syncthreads();
    if (t == 0) {
        int flag = 0;
        if (c_i32 >= 32) flag = 1;
        else if (c_f32 >= 32) flag = 2;
        g_qflag = flag;
    }
}

// ---------------------------------------------------------------------------
// Kernel 1: convert x (float32, fp16-exact values) -> fp16 scratch.
// ---------------------------------------------------------------------------
__global__ void __launch_bounds__(256) convert_x_kernel(const float* __restrict__ x)
{
    const int i = blockIdx.x * blockDim.x + threadIdx.x;   // 65536 threads, 4 elems each
    float4 f = ((const float4*)x)[i];
    __half2 h0 = __floats2half2_rn(f.x, f.y);
    __half2 h1 = __floats2half2_rn(f.z, f.w);
    uint2 p;
    p.x = *(unsigned*)&h0;
    p.y = *(unsigned*)&h1;
    ((uint2*)g_x)[i] = p;
}

// ---------------------------------------------------------------------------
// Kernel 2: dequantize. One CTA per 1024-element quant block.
// int8 positions reconstructed from fp16_pos (sorted outlier positions):
// compact index = p - (#outliers before p). Avoids reading int8_pos/block_idx.
// ---------------------------------------------------------------------------
__device__ __forceinline__ int lower_bound_i32(const int* __restrict__ a, int n, int v) {
    int lo = 0, hi = n;
    while (lo < hi) {
        int mid = (lo + hi) >> 1;
        if (a[mid] < v) lo = mid + 1; else hi = mid;
    }
    return lo;
}

__global__ void __launch_bounds__(128) dequant_kernel(
    const void*  __restrict__ qdata,
    const float* __restrict__ fp16_data,   // outlier values (fp16-exact f32)
    const float* __restrict__ scales,      // fp16-exact f32
    const int*   __restrict__ fp16_pos,
    int n_fp16)
{
    __shared__ int   s_bounds[2];
    __shared__ int   s_opos[BLOCK_SIZE];
    __shared__ float s_oval[BLOCK_SIZE];

    const int b    = blockIdx.x;
    const int t    = threadIdx.x;
    const int base = b << 10;

    if (t < 2) s_bounds[t] = lower_bound_i32(fp16_pos, n_fp16, base + t * BLOCK_SIZE);
    __syncthreads();

    const int o_start = s_bounds[0];
    const int cnt     = s_bounds[1] - s_bounds[0];

    for (int i = t; i < cnt; i += 128) {
        s_opos[i] = fp16_pos[o_start + i] - base;
        s_oval[i] = fp16_data[o_start + i];
    }
    __syncthreads();

    const long  ibase = (long)base - o_start;   // compact index of this block's first int8
    const float sc    = scales[b];
    const int   lp0   = t * 8;

    int j = 0;
    while (j < cnt && s_opos[j] < lp0) j++;

    bool outl[8];
    int  crel[8];
    float v[8];
    #pragma unroll
    for (int s = 0; s < 8; s++) {
        const int lp = lp0 + s;
        if (j < cnt && s_opos[j] == lp) {
            outl[s] = true;
            v[s]    = s_oval[j];
            crel[s] = 0;
            j++;
        } else {
            outl[s] = false;
            crel[s] = lp - j;    // compact index within block (valid, < block int8 count)
        }
    }

    const int flag = g_qflag;   // uniform branch
    if (flag == 0) {
        const int8_t* q = (const int8_t*)qdata;
        #pragma unroll
        for (int s = 0; s < 8; s++)
            if (!outl[s]) v[s] = (float)q[ibase + crel[s]] * sc;
    } else if (flag == 1) {
        const int* q = (const int*)qdata;
        #pragma unroll
        for (int s = 0; s < 8; s++)
            if (!outl[s]) v[s] = (float)q[ibase + crel[s]] * sc;
    } else {
        const float* q = (const float*)qdata;
        #pragma unroll
        for (int s = 0; s < 8; s++)
            if (!outl[s]) v[s] = q[ibase + crel[s]] * sc;
    }

    unsigned r[4];
    #pragma unroll
    for (int p = 0; p < 4; p++) {
        __half2 h = __floats2half2_rn(v[2 * p], v[2 * p + 1]);
        r[p] = *(unsigned*)&h;
    }
    uint4 pack; pack.x = r[0]; pack.y = r[1]; pack.z = r[2]; pack.w = r[3];
    *(uint4*)(g_W + base + lp0) = pack;
}

// ---------------------------------------------------------------------------
// Kernel 3: out[64,11008] = x[64,4096] @ W[11008,4096]^T + bias (float32 out)
// CTA tile 64M x 64N, 4 warps. K-chunks of 64, 4-stage cp.async pipeline,
// mma.sync m16n8k16 f16f16->f32.
// ---------------------------------------------------------------------------
#define KC      64
#define NK      (IN_FEATURES / KC)   // 64
#define STAGES  4
#define SSTRIDE 72                   // halves per row (64 + 8 pad, 16B aligned)
#define STAGE_HALVES (64 * SSTRIDE)  // 4608

__device__ __forceinline__ void cp_async16(void* smem_ptr, const void* gmem_ptr) {
    unsigned saddr = (unsigned)__cvta_generic_to_shared(smem_ptr);
    asm volatile("cp.async.cg.shared.global [%0], [%1], 16;\n" :: "r"(saddr), "l"(gmem_ptr));
}
__device__ __forceinline__ void cp_commit() {
    asm volatile("cp.async.commit_group;\n");
}
template <int N>
__device__ __forceinline__ void cp_wait() {
    asm volatile("cp.async.wait_group %0;\n" :: "n"(N));
}

__global__ void __launch_bounds__(128) gemm_kernel(
    const float* __restrict__ bias,
    float* __restrict__ out)
{
    extern __shared__ __half smem[];
    __half* As = smem;                           // [STAGES][64][SSTRIDE]
    __half* Bs = smem + STAGES * STAGE_HALVES;

    const int n0   = blockIdx.x * 64;
    const int t    = threadIdx.x;
    const int warp = t >> 5;
    const int lane = t & 31;
    const int g    = lane >> 2;
    const int tid4 = lane & 3;

    const __half* X = g_x;
    const __half* W = g_W;

    auto load_stage = [&](int kc, int st) {
        const int k0 = kc * KC;
        __half* A = As + st * STAGE_HALVES;
        __half* B = Bs + st * STAGE_HALVES;
        #pragma unroll
        for (int q = 0; q < 4; q++) {
            const int idx = t + q * 128;         // 0..511
            const int row = idx >> 3;            // 0..63
            const int seg = idx & 7;             // 16B segments
            cp_async16(A + row * SSTRIDE + seg * 8,
                       X + row * IN_FEATURES + k0 + seg * 8);
            cp_async16(B + row * SSTRIDE + seg * 8,
                       W + (long)(n0 + row) * IN_FEATURES + k0 + seg * 8);
        }
        cp_commit();
    };

    float acc[8][4];
    #pragma unroll
    for (int n = 0; n < 8; n++)
        #pragma unroll
        for (int i = 0; i < 4; i++) acc[n][i] = 0.0f;

    load_stage(0, 0);
    load_stage(1, 1);
    load_stage(2, 2);

    for (int kc = 0; kc < NK; kc++) {
        const int st = kc & (STAGES - 1);
        const int rem = NK - 1 - kc;
        if (rem >= 2)      cp_wait<2>();
        else if (rem == 1) cp_wait<1>();
        else               cp_wait<0>();
        __syncthreads();

        if (kc + 3 < NK) load_stage(kc + 3, (kc + 3) & (STAGES - 1));

        const __half* A = As + st * STAGE_HALVES;
        const __half* B = Bs + st * STAGE_HALVES;

        #pragma unroll
        for (int ks = 0; ks < 4; ks++) {
            const int kb = ks * 16;
            unsigned a0, a1, a2, a3;
            {
                const __half* p0 = A + (warp * 16 + g) * SSTRIDE + kb + tid4 * 2;
                const __half* p8 = A + (warp * 16 + g + 8) * SSTRIDE + kb + tid4 * 2;
                a0 = *(const unsigned*)p0;
                a2 = *(const unsigned*)(p0 + 8);
                a1 = *(const unsigned*)p8;
                a3 = *(const unsigned*)(p8 + 8);
            }
            #pragma unroll
            for (int n = 0; n < 8; n++) {
                const __half* pb = B + (n * 8 + g) * SSTRIDE + kb + tid4 * 2;
                unsigned b0 = *(const unsigned*)pb;
                unsigned b1 = *(const unsigned*)(pb + 8);
                asm volatile(
                    "mma.sync.aligned.m16n8k16.row.col.f32.f16.f16.f32 "
                    "{%0,%1,%2,%3}, {%4,%5,%6,%7}, {%8,%9}, {%0,%1,%2,%3};\n"
                    : "+f"(acc[n][0]), "+f"(acc[n][1]), "+f"(acc[n][2]), "+f"(acc[n][3])
                    : "r"(a0), "r"(a1), "r"(a2), "r"(a3), "r"(b0), "r"(b1));
            }
        }
        __syncthreads();
    }

    // Epilogue: mimic reference fp16 rounding: fp16(dot) + fp16 bias in fp16,
    // emit float32.
    #pragma unroll
    for (int n = 0; n < 8; n++) {
        const int col = n0 + n * 8 + tid4 * 2;
        const __half hb0 = __float2half_rn(bias[col]);
        const __half hb1 = __float2half_rn(bias[col + 1]);
        const int row0 = warp * 16 + g;
        const int row1 = row0 + 8;
        float2 o0, o1;
        o0.x = __half2float(__hadd(__float2half_rn(acc[n][0]), hb0));
        o0.y = __half2float(__hadd(__float2half_rn(acc[n][1]), hb1));
        o1.x = __half2float(__hadd(__float2half_rn(acc[n][2]), hb0));
        o1.y = __half2float(__hadd(__float2half_rn(acc[n][3]), hb1));
        *(float2*)(out + (long)row0 * OUT_FEATURES + col) = o0;
        *(float2*)(out + (long)row1 * OUT_FEATURES + col) = o1;
    }
}

// ---------------------------------------------------------------------------
// Launch. Input order: x, int8_data, fp16_data, scales, bias, int8_pos,
// fp16_pos, block_idx. int8_pos/block_idx unused by design.
// All float16 tensors are delivered as float32 by the harness; output float32.
// ---------------------------------------------------------------------------
extern "C" void kernel_launch(void* const* d_in, const int* in_sizes, int n_in,
                              void* d_out, int out_size)
{
    const float* x         = (const float*)d_in[0];
    const void*  int8_data = d_in[1];
    const float* fp16_data = (const float*)d_in[2];
    const float* scales    = (const float*)d_in[3];
    const float* bias      = (const float*)d_in[4];
    const int*   fp16_pos  = (const int*)d_in[6];
    const int    n_fp16    = in_sizes[2];

    detect_kernel<<<1, 64>>>(int8_data);
    convert_x_kernel<<<TOKENS * IN_FEATURES / (256 * 4), 256>>>(x);
    dequant_kernel<<<NUM_BLOCKS, 128>>>(int8_data, fp16_data, scales, fp16_pos, n_fp16);

    const int smem_bytes = 2 * STAGES * STAGE_HALVES * (int)sizeof(__half); // 73728
    static bool attr_set = false;
    if (!attr_set) {
        cudaFuncSetAttribute(gemm_kernel,
                             cudaFuncAttributeMaxDynamicSharedMemorySize, smem_bytes);
        attr_set = true;
    }
    gemm_kernel<<<OUT_FEATURES / 64, 128, smem_bytes>>>(bias, (float*)d_out);
}

// round 5
// speedup vs baseline: 1.6743x; 1.6743x over previous
#include <cuda_runtime.h>
#include <cuda_fp16.h>
#include <cstdint>
#include <math.h>

// Problem constants (fixed for this problem instance)
#define OUT_FEATURES 11008
#define IN_FEATURES  4096
#define TOKENS       64
#define BLOCK_SIZE   1024
#define NUM_BLOCKS   (OUT_FEATURES * IN_FEATURES / BLOCK_SIZE)   // 44032
#define W_ELEMS      ((long)OUT_FEATURES * IN_FEATURES)          // 45,088,768
#define KSPLIT       4

// Scratch (no allocation allowed -> device globals)
__device__ __half g_W[W_ELEMS];                        // dequantized weights, fp16
__device__ __half g_x[TOKENS * IN_FEATURES];           // x converted to fp16
__device__ int    g_qflag;                             // 0=int8, 1=int32, 2=float32
__device__ int    g_ostart[NUM_BLOCKS + 1];            // outlier lower_bound per block
__device__ float  g_part[KSPLIT][TOKENS * OUT_FEATURES]; // split-K partials (11.3 MB)

// ---------------------------------------------------------------------------
// Kernel 0: detect storage layout of int8_data (harness may upcast).
// ---------------------------------------------------------------------------
__global__ void detect_kernel(const void* __restrict__ qdata)
{
    __shared__ int c_i32, c_f32;
    if (threadIdx.x == 0) { c_i32 = 0; c_f32 = 0; }
    __syncthreads();
    const int t = threadIdx.x;   // 64 threads
    int w = ((const int*)qdata)[t];
    bool vi32 = (w >= -127 && w <= 127);
    float f = __int_as_float(w);
    bool vf32 = (!vi32) && isfinite(f) && fabsf(f) <= 127.0f && f == truncf(f);
    if (vi32) atomicAdd(&c_i32, 1);
    if (vf32) atomicAdd(&c_f32, 1);
    __syncthreads();
    if (t == 0) {
        int flag = 0;
        if (c_i32 >= 32) flag = 1;
        else if (c_f32 >= 32) flag = 2;
        g_qflag = flag;
    }
}

// ---------------------------------------------------------------------------
// Kernel 1: convert x (float32, fp16-exact) -> fp16 scratch.
// ---------------------------------------------------------------------------
__global__ void __launch_bounds__(256) convert_x_kernel(const float* __restrict__ x)
{
    const int i = blockIdx.x * blockDim.x + threadIdx.x;
    float4 f = ((const float4*)x)[i];
    __half2 h0 = __floats2half2_rn(f.x, f.y);
    __half2 h1 = __floats2half2_rn(f.z, f.w);
    uint2 p;
    p.x = *(unsigned*)&h0;
    p.y = *(unsigned*)&h1;
    ((uint2*)g_x)[i] = p;
}

// ---------------------------------------------------------------------------
// Kernel 2: invert fp16_pos -> per-block outlier lower bounds.
// For each i in [0, n_fp16], blocks b with
//   floor(p_{i-1}/1024)+1 <= b <= floor(p_i/1024)    (p_{-1}=-1, p_n=numel)
// have g_ostart[b] = i. Every entry [0, NUM_BLOCKS] written exactly once.
// ---------------------------------------------------------------------------
__global__ void __launch_bounds__(256) ostart_kernel(
    const int* __restrict__ fp16_pos, int n_fp16)
{
    const int stride = gridDim.x * blockDim.x;
    for (int i = blockIdx.x * blockDim.x + threadIdx.x; i <= n_fp16; i += stride) {
        int lo = (i == 0) ? 0 : ((fp16_pos[i - 1] >> 10) + 1);
        int hi = (i == n_fp16) ? NUM_BLOCKS : (fp16_pos[i] >> 10);
        for (int b = lo; b <= hi; b++) g_ostart[b] = i;
    }
}

// ---------------------------------------------------------------------------
// Kernel 3: dequantize. One CTA per 1024-elem quant block, no smem, no sync.
// Compact int8 index of flat pos p = p - (#outliers before p).
// ---------------------------------------------------------------------------
__global__ void __launch_bounds__(128) dequant_kernel(
    const void*  __restrict__ qdata,
    const float* __restrict__ fp16_data,
    const float* __restrict__ scales,
    const int*   __restrict__ fp16_pos)
{
    const int b    = blockIdx.x;
    const int t    = threadIdx.x;
    const int base = b << 10;

    const int o_s = g_ostart[b];
    const int o_e = g_ostart[b + 1];
    const long ibase = (long)base - o_s;     // compact index of block's first int8
    const float sc   = scales[b];
    const int   lp0  = t * 8;

    // advance j to first outlier >= lp0 (few iterations; L1-cached)
    int j = o_s;
    while (j < o_e && (fp16_pos[j] - base) < lp0) j++;

    bool  outl[8];
    int   crel[8];
    float v[8];
    #pragma unroll
    for (int s = 0; s < 8; s++) {
        const int lp = lp0 + s;
        if (j < o_e && (fp16_pos[j] - base) == lp) {
            outl[s] = true;
            v[s]    = fp16_data[j];
            crel[s] = 0;
            j++;
        } else {
            outl[s] = false;
            crel[s] = lp - (j - o_s);   // local compact offset within block
        }
    }

    const int flag = g_qflag;
    if (flag == 0) {
        const int8_t* q = (const int8_t*)qdata;
        #pragma unroll
        for (int s = 0; s < 8; s++)
            if (!outl[s]) v[s] = (float)q[ibase + crel[s]] * sc;
    } else if (flag == 1) {
        const int* q = (const int*)qdata;
        #pragma unroll
        for (int s = 0; s < 8; s++)
            if (!outl[s]) v[s] = (float)q[ibase + crel[s]] * sc;
    } else {
        const float* q = (const float*)qdata;
        #pragma unroll
        for (int s = 0; s < 8; s++)
            if (!outl[s]) v[s] = q[ibase + crel[s]] * sc;
    }

    unsigned r[4];
    #pragma unroll
    for (int p = 0; p < 4; p++) {
        __half2 h = __floats2half2_rn(v[2 * p], v[2 * p + 1]);
        r[p] = *(unsigned*)&h;
    }
    uint4 pack; pack.x = r[0]; pack.y = r[1]; pack.z = r[2]; pack.w = r[3];
    *(uint4*)(g_W + base + lp0) = pack;
}

// ---------------------------------------------------------------------------
// Kernel 4: split-K GEMM. grid (172, KSPLIT). CTA: 64M x 64N, K range 1024.
// 3-stage cp.async pipeline, chunks of 64. Partials (f32, no bias) -> g_part.
// ---------------------------------------------------------------------------
#define KC      64
#define KPS     (IN_FEATURES / KSPLIT)   // 1024 per split
#define NKC     (KPS / KC)               // 16 chunks
#define STAGES  3
#define SSTRIDE 72                        // halves per row (64 + 8 pad, 16B align)
#define STAGE_HALVES (64 * SSTRIDE)       // 4608

__device__ __forceinline__ void cp_async16(void* smem_ptr, const void* gmem_ptr) {
    unsigned saddr = (unsigned)__cvta_generic_to_shared(smem_ptr);
    asm volatile("cp.async.cg.shared.global [%0], [%1], 16;\n" :: "r"(saddr), "l"(gmem_ptr));
}
__device__ __forceinline__ void cp_commit() {
    asm volatile("cp.async.commit_group;\n");
}
template <int N>
__device__ __forceinline__ void cp_wait() {
    asm volatile("cp.async.wait_group %0;\n" :: "n"(N));
}

__global__ void __launch_bounds__(128) gemm_kernel()
{
    extern __shared__ __half smem[];
    __half* As = smem;                           // [STAGES][64][SSTRIDE]
    __half* Bs = smem + STAGES * STAGE_HALVES;

    const int n0   = blockIdx.x * 64;
    const int kz   = blockIdx.y;
    const int kbase = kz * KPS;
    const int t    = threadIdx.x;
    const int warp = t >> 5;
    const int lane = t & 31;
    const int g    = lane >> 2;
    const int tid4 = lane & 3;

    const __half* X = g_x;
    const __half* W = g_W;

    auto load_stage = [&](int kc, int st) {
        const int k0 = kbase + kc * KC;
        __half* A = As + st * STAGE_HALVES;
        __half* B = Bs + st * STAGE_HALVES;
        #pragma unroll
        for (int q = 0; q < 4; q++) {
            const int idx = t + q * 128;         // 0..511
            const int row = idx >> 3;            // 0..63
            const int seg = idx & 7;             // 16B segments
            cp_async16(A + row * SSTRIDE + seg * 8,
                       X + row * IN_FEATURES + k0 + seg * 8);
            cp_async16(B + row * SSTRIDE + seg * 8,
                       W + (long)(n0 + row) * IN_FEATURES + k0 + seg * 8);
        }
        cp_commit();
    };

    float acc[8][4];
    #pragma unroll
    for (int n = 0; n < 8; n++)
        #pragma unroll
        for (int i = 0; i < 4; i++) acc[n][i] = 0.0f;

    load_stage(0, 0);
    load_stage(1, 1);

    for (int kc = 0; kc < NKC; kc++) {
        const int st = kc % STAGES;
        if (kc == NKC - 1) cp_wait<0>(); else cp_wait<1>();
        __syncthreads();

        if (kc + 2 < NKC) load_stage(kc + 2, (kc + 2) % STAGES);

        const __half* A = As + st * STAGE_HALVES;
        const __half* B = Bs + st * STAGE_HALVES;

        #pragma unroll
        for (int ks = 0; ks < 4; ks++) {
            const int kb = ks * 16;
            unsigned a0, a1, a2, a3;
            {
                const __half* p0 = A + (warp * 16 + g) * SSTRIDE + kb + tid4 * 2;
                const __half* p8 = A + (warp * 16 + g + 8) * SSTRIDE + kb + tid4 * 2;
                a0 = *(const unsigned*)p0;
                a2 = *(const unsigned*)(p0 + 8);
                a1 = *(const unsigned*)p8;
                a3 = *(const unsigned*)(p8 + 8);
            }
            #pragma unroll
            for (int n = 0; n < 8; n++) {
                const __half* pb = B + (n * 8 + g) * SSTRIDE + kb + tid4 * 2;
                unsigned b0 = *(const unsigned*)pb;
                unsigned b1 = *(const unsigned*)(pb + 8);
                asm volatile(
                    "mma.sync.aligned.m16n8k16.row.col.f32.f16.f16.f32 "
                    "{%0,%1,%2,%3}, {%4,%5,%6,%7}, {%8,%9}, {%0,%1,%2,%3};\n"
                    : "+f"(acc[n][0]), "+f"(acc[n][1]), "+f"(acc[n][2]), "+f"(acc[n][3])
                    : "r"(a0), "r"(a1), "r"(a2), "r"(a3), "r"(b0), "r"(b1));
            }
        }
        __syncthreads();
    }

    // Write raw f32 partials (bias added in reduce kernel).
    float* part = g_part[kz];
    #pragma unroll
    for (int n = 0; n < 8; n++) {
        const int col = n0 + n * 8 + tid4 * 2;
        const int row0 = warp * 16 + g;
        const int row1 = row0 + 8;
        float2 o0 = make_float2(acc[n][0], acc[n][1]);
        float2 o1 = make_float2(acc[n][2], acc[n][3]);
        *(float2*)(part + (long)row0 * OUT_FEATURES + col) = o0;
        *(float2*)(part + (long)row1 * OUT_FEATURES + col) = o1;
    }
}

// ---------------------------------------------------------------------------
// Kernel 5: reduce split-K partials + bias (fp16-rounding mimic of reference).
// ---------------------------------------------------------------------------
__global__ void __launch_bounds__(256) reduce_kernel(
    const float* __restrict__ bias, float* __restrict__ out)
{
    const int i4 = blockIdx.x * blockDim.x + threadIdx.x;  // float4 index
    const long e0 = (long)i4 * 4;
    const int col = (int)(e0 % OUT_FEATURES);

    float4 s  = *(const float4*)&g_part[0][e0];
    float4 s1 = *(const float4*)&g_part[1][e0];
    float4 s2 = *(const float4*)&g_part[2][e0];
    float4 s3 = *(const float4*)&g_part[3][e0];
    s.x += s1.x + s2.x + s3.x;
    s.y += s1.y + s2.y + s3.y;
    s.z += s1.z + s2.z + s3.z;
    s.w += s1.w + s2.w + s3.w;

    float4 bf = *(const float4*)(bias + col);

    float4 o;
    o.x = __half2float(__hadd(__float2half_rn(s.x), __float2half_rn(bf.x)));
    o.y = __half2float(__hadd(__float2half_rn(s.y), __float2half_rn(bf.y)));
    o.z = __half2float(__hadd(__float2half_rn(s.z), __float2half_rn(bf.z)));
    o.w = __half2float(__hadd(__float2half_rn(s.w), __float2half_rn(bf.w)));
    *(float4*)(out + e0) = o;
}

// ---------------------------------------------------------------------------
// Launch. Input order: x, int8_data, fp16_data, scales, bias, int8_pos,
// fp16_pos, block_idx. int8_pos/block_idx unused by design.
// ---------------------------------------------------------------------------
extern "C" void kernel_launch(void* const* d_in, const int* in_sizes, int n_in,
                              void* d_out, int out_size)
{
    const float* x         = (const float*)d_in[0];
    const void*  int8_data = d_in[1];
    const float* fp16_data = (const float*)d_in[2];
    const float* scales    = (const float*)d_in[3];
    const float* bias      = (const float*)d_in[4];
    const int*   fp16_pos  = (const int*)d_in[6];
    const int    n_fp16    = in_sizes[2];

    detect_kernel<<<1, 64>>>(int8_data);
    convert_x_kernel<<<TOKENS * IN_FEATURES / (256 * 4), 256>>>(x);
    ostart_kernel<<<256, 256>>>(fp16_pos, n_fp16);
    dequant_kernel<<<NUM_BLOCKS, 128>>>(int8_data, fp16_data, scales, fp16_pos);

    const int smem_bytes = 2 * STAGES * STAGE_HALVES * (int)sizeof(__half); // 55296
    static bool attr_set = false;
    if (!attr_set) {
        cudaFuncSetAttribute(gemm_kernel,
                             cudaFuncAttributeMaxDynamicSharedMemorySize, smem_bytes);
        attr_set = true;
    }
    gemm_kernel<<<dim3(OUT_FEATURES / 64, KSPLIT), 128, smem_bytes>>>();

    reduce_kernel<<<TOKENS * OUT_FEATURES / (256 * 4), 256>>>(bias, (float*)d_out);
}